// round 11
// baseline (speedup 1.0000x reference)
#include <cuda_runtime.h>
#include <cuda_fp16.h>
#include <cuda_bf16.h>
#include <math.h>

#define NN   50000
#define EE   600000
#define D    128
#define OUTD 64
#define NBLK ((NN + 255) / 256)

// ---------------- scratch (device globals; no allocation) ----------------
__device__ int      g_is64;
__device__ int      g_cnt[NN];
__device__ int      g_part[NBLK];
__device__ int      g_off[NN + 1];
__device__ int      g_fill[NN + 1];
__device__ int      g_csr_src[EE];
__device__ __half   g_h   [(size_t)NN * D];
__device__ float    g_bufA[(size_t)NN * D];
__device__ float    g_si[NN];
__device__ float    g_sj[NN];
__device__ float    g_Wc[D * OUTD];
__device__ float    g_bc[OUTD];

// ---------------- detect dtype + zero histogram ----------------
__global__ void k_detect(const void* ei) {
    int i = blockIdx.x * 256 + threadIdx.x;
    if (i < NN) g_cnt[i] = 0;
    if (blockIdx.x == 0 && threadIdx.x < 32) {
        const long long* p = (const long long*)ei;
        long long v = p[threadIdx.x];
        int bad = (v < 0 || v >= NN) ? 1 : 0;
        unsigned b = __ballot_sync(0xffffffffu, bad);
        if (threadIdx.x == 0) g_is64 = (b == 0) ? 1 : 0;
    }
}

__device__ __forceinline__ void load_edge(const void* ei, int i, int& s, int& d) {
    if (g_is64) {
        const long long* p = (const long long*)ei;
        s = (int)p[i];
        d = (int)p[(size_t)EE + i];
    } else {
        const int* p = (const int*)ei;
        s = p[i];
        d = p[EE + i];
    }
}

__global__ void k_hist(const void* ei) {
    int i = blockIdx.x * blockDim.x + threadIdx.x;
    if (i >= EE) return;
    int d;
    if (g_is64) {
        const long long* p = (const long long*)ei;
        d = (int)p[(size_t)EE + i];
    } else {
        const int* p = (const int*)ei;
        d = p[EE + i];
    }
    atomicAdd(&g_cnt[d], 1);
}

// ---------------- scan ----------------
__global__ void k_scanA() {
    __shared__ int sw[8];
    int b = blockIdx.x;
    int i = b * 256 + threadIdx.x;
    int v = (i < NN) ? g_cnt[i] : 0;
    int lane = threadIdx.x & 31, wid = threadIdx.x >> 5;
#pragma unroll
    for (int o = 16; o > 0; o >>= 1) v += __shfl_xor_sync(0xffffffffu, v, o);
    if (lane == 0) sw[wid] = v;
    __syncthreads();
    if (threadIdx.x == 0) {
        int s = 0;
#pragma unroll
        for (int w = 0; w < 8; w++) s += sw[w];
        g_part[b] = s;
    }
}

__global__ void k_scanC() {
    __shared__ int sw[8];
    __shared__ int sbase;
    int b = blockIdx.x;
    int i = b * 256 + threadIdx.x;
    int lane = threadIdx.x & 31, wid = threadIdx.x >> 5;
    int v = (i < NN) ? g_cnt[i] : 0;
    int x = v;
#pragma unroll
    for (int o = 1; o < 32; o <<= 1) {
        int t = __shfl_up_sync(0xffffffffu, x, o);
        if (lane >= o) x += t;
    }
    if (lane == 31) sw[wid] = x;
    if (wid == 1) {
        int s = 0;
        for (int j = lane; j < b; j += 32) s += g_part[j];
#pragma unroll
        for (int o = 16; o > 0; o >>= 1) s += __shfl_xor_sync(0xffffffffu, s, o);
        if (lane == 0) sbase = s;
    }
    __syncthreads();
    if (wid == 0 && lane < 8) {
        int y = sw[lane];
#pragma unroll
        for (int o = 1; o < 8; o <<= 1) {
            int t = __shfl_up_sync(0xffu, y, o);
            if (lane >= o) y += t;
        }
        sw[lane] = y;
    }
    __syncthreads();
    int incl = x + (wid ? sw[wid - 1] : 0) + sbase;
    if (i < NN) { g_off[i + 1] = incl; g_fill[i + 1] = incl; }
    if (i == 0) { g_off[0] = 0; g_fill[0] = 0; }
}

__global__ void k_reorder(const void* ei) {
    int i = blockIdx.x * blockDim.x + threadIdx.x;
    if (i >= EE) return;
    int s, d;
    load_edge(ei, i, s, d);
    int pos = atomicAdd(&g_fill[d], 1);
    g_csr_src[pos] = s;
}

// ---------------- tf32 helpers ----------------
__device__ __forceinline__ unsigned f2tf32(float f) {
    unsigned u;
    asm("cvt.rna.tf32.f32 %0, %1;" : "=r"(u) : "f"(f));
    return u;
}
__device__ __forceinline__ uint2 split_tf32(float f) {
    unsigned hi = f2tf32(f);
    float r = f - __uint_as_float(hi);
    unsigned lo = f2tf32(r);
    return make_uint2(hi, lo);
}
__device__ __forceinline__ void mma8(float* c, unsigned a0, unsigned a1, unsigned a2, unsigned a3,
                                     unsigned b0, unsigned b1) {
    asm volatile("mma.sync.aligned.m16n8k8.row.col.f32.tf32.tf32.f32 "
                 "{%0,%1,%2,%3}, {%4,%5,%6,%7}, {%8,%9}, {%0,%1,%2,%3};"
                 : "+f"(c[0]), "+f"(c[1]), "+f"(c[2]), "+f"(c[3])
                 : "r"(a0), "r"(a1), "r"(a2), "r"(a3), "r"(b0), "r"(b1));
}

// ---------------- GEMM: 64x128 tile, 4 warps (2m x 2n), 3xTF32 mma, fp16 Y ----------------
__global__ void __launch_bounds__(128)
k_gemm(const float* __restrict__ X, const float* __restrict__ W,
       const float* __restrict__ bias, const float* __restrict__ att,
       __half* __restrict__ Y, int nrows) {
    __shared__ uint2 As[2][64][10];    // [buf][row][k] k-chunk=8, pad 10
    __shared__ uint2 Bs[2][8][132];    // [buf][k][n]
    __shared__ float sSi[64][2], sSj[64][2];

    int t = threadIdx.x;
    int lane = t & 31, wid = t >> 5;
    int warp_m = wid >> 1, warp_n = wid & 1;
    int g = lane >> 2, tc = lane & 3;
    int row0 = blockIdx.x * 64;

    float c[2][8][4];
#pragma unroll
    for (int mf = 0; mf < 2; mf++)
#pragma unroll
        for (int nf = 0; nf < 8; nf++)
#pragma unroll
            for (int q = 0; q < 4; q++) c[mf][nf][q] = 0.f;

    int a_row = t >> 1, a_kq = (t & 1) * 4;
    int b_k[2], b_nq[2];
#pragma unroll
    for (int l = 0; l < 2; l++) {
        int idx = t + l * 128;
        b_k[l]  = idx >> 5;
        b_nq[l] = (idx & 31) * 4;
    }

    float4 av, bv[2];
    {
        int gr = row0 + a_row;
        av = make_float4(0.f, 0.f, 0.f, 0.f);
        if (gr < nrows) av = *(const float4*)&X[(size_t)gr * D + a_kq];
#pragma unroll
        for (int l = 0; l < 2; l++)
            bv[l] = *(const float4*)&W[(size_t)b_k[l] * D + b_nq[l]];
    }
    {
        As[0][a_row][a_kq + 0] = split_tf32(av.x);
        As[0][a_row][a_kq + 1] = split_tf32(av.y);
        As[0][a_row][a_kq + 2] = split_tf32(av.z);
        As[0][a_row][a_kq + 3] = split_tf32(av.w);
#pragma unroll
        for (int l = 0; l < 2; l++) {
            Bs[0][b_k[l]][b_nq[l] + 0] = split_tf32(bv[l].x);
            Bs[0][b_k[l]][b_nq[l] + 1] = split_tf32(bv[l].y);
            Bs[0][b_k[l]][b_nq[l] + 2] = split_tf32(bv[l].z);
            Bs[0][b_k[l]][b_nq[l] + 3] = split_tf32(bv[l].w);
        }
    }
    __syncthreads();

    for (int kt = 0; kt < 16; kt++) {
        int cur = kt & 1;
        if (kt < 15) {
            int kb = (kt + 1) * 8;
            int gr = row0 + a_row;
            av = make_float4(0.f, 0.f, 0.f, 0.f);
            if (gr < nrows) av = *(const float4*)&X[(size_t)gr * D + kb + a_kq];
#pragma unroll
            for (int l = 0; l < 2; l++)
                bv[l] = *(const float4*)&W[(size_t)(kb + b_k[l]) * D + b_nq[l]];
        }
        unsigned ah[2][4], al[2][4];
#pragma unroll
        for (int mf = 0; mf < 2; mf++) {
            int r = warp_m * 32 + mf * 16 + g;
            uint2 x00 = As[cur][r][tc];
            uint2 x10 = As[cur][r + 8][tc];
            uint2 x01 = As[cur][r][tc + 4];
            uint2 x11 = As[cur][r + 8][tc + 4];
            ah[mf][0] = x00.x; ah[mf][1] = x10.x; ah[mf][2] = x01.x; ah[mf][3] = x11.x;
            al[mf][0] = x00.y; al[mf][1] = x10.y; al[mf][2] = x01.y; al[mf][3] = x11.y;
        }
#pragma unroll
        for (int nf = 0; nf < 8; nf++) {
            int n = warp_n * 64 + nf * 8 + g;
            uint2 y0 = Bs[cur][tc][n];
            uint2 y1 = Bs[cur][tc + 4][n];
#pragma unroll
            for (int mf = 0; mf < 2; mf++) {
                mma8(c[mf][nf], al[mf][0], al[mf][1], al[mf][2], al[mf][3], y0.x, y1.x); // lo*hi
                mma8(c[mf][nf], ah[mf][0], ah[mf][1], ah[mf][2], ah[mf][3], y0.y, y1.y); // hi*lo
                mma8(c[mf][nf], ah[mf][0], ah[mf][1], ah[mf][2], ah[mf][3], y0.x, y1.x); // hi*hi
            }
        }
        if (kt < 15) {
            int nxt = 1 - cur;
            As[nxt][a_row][a_kq + 0] = split_tf32(av.x);
            As[nxt][a_row][a_kq + 1] = split_tf32(av.y);
            As[nxt][a_row][a_kq + 2] = split_tf32(av.z);
            As[nxt][a_row][a_kq + 3] = split_tf32(av.w);
#pragma unroll
            for (int l = 0; l < 2; l++) {
                Bs[nxt][b_k[l]][b_nq[l] + 0] = split_tf32(bv[l].x);
                Bs[nxt][b_k[l]][b_nq[l] + 1] = split_tf32(bv[l].y);
                Bs[nxt][b_k[l]][b_nq[l] + 2] = split_tf32(bv[l].z);
                Bs[nxt][b_k[l]][b_nq[l] + 3] = split_tf32(bv[l].w);
            }
            __syncthreads();
        }
    }

    // epilogue: bias add, fp16 Y store, si/sj reduction (fp32)
#pragma unroll
    for (int mf = 0; mf < 2; mf++) {
        int rA = warp_m * 32 + mf * 16 + g;
        int rB = rA + 8;
        int grA = row0 + rA, grB = row0 + rB;
        float siA = 0.f, sjA = 0.f, siB = 0.f, sjB = 0.f;
#pragma unroll
        for (int nf = 0; nf < 8; nf++) {
            int col = warp_n * 64 + nf * 8 + tc * 2;
            float b0 = bias[col], b1 = bias[col + 1];
            float z0 = c[mf][nf][0] + b0, z1 = c[mf][nf][1] + b1;
            float z2 = c[mf][nf][2] + b0, z3 = c[mf][nf][3] + b1;
            if (grA < nrows) *(__half2*)&Y[(size_t)grA * D + col] = __floats2half2_rn(z0, z1);
            if (grB < nrows) *(__half2*)&Y[(size_t)grB * D + col] = __floats2half2_rn(z2, z3);
            float ai0 = att[col], ai1 = att[col + 1];
            float aj0 = att[D + col], aj1 = att[D + col + 1];
            siA = fmaf(z0, ai0, fmaf(z1, ai1, siA));
            sjA = fmaf(z0, aj0, fmaf(z1, aj1, sjA));
            siB = fmaf(z2, ai0, fmaf(z3, ai1, siB));
            sjB = fmaf(z2, aj0, fmaf(z3, aj1, sjB));
        }
#pragma unroll
        for (int o = 1; o < 4; o <<= 1) {
            siA += __shfl_xor_sync(0xffffffffu, siA, o);
            sjA += __shfl_xor_sync(0xffffffffu, sjA, o);
            siB += __shfl_xor_sync(0xffffffffu, siB, o);
            sjB += __shfl_xor_sync(0xffffffffu, sjB, o);
        }
        if (tc == 0) {
            sSi[rA][warp_n] = siA; sSj[rA][warp_n] = sjA;
            sSi[rB][warp_n] = siB; sSj[rB][warp_n] = sjB;
        }
    }
    __syncthreads();
    if (t < 64) {
        int gr = row0 + t;
        if (gr < nrows) {
            g_si[gr] = sSi[t][0] + sSi[t][1];
            g_sj[gr] = sSj[t][0] + sSj[t][1];
        }
    }
}

// ---------------- fused edge kernel: fp16 h gather (halved traffic) ----------------
#define WPB 8
__global__ void k_edge(const __half* __restrict__ h, const float* __restrict__ bias,
                       float* __restrict__ out) {
    __shared__ float sAlpha[WPB][64];
    __shared__ int   sSrc[WPB][64];
    int wi = threadIdx.x >> 5;
    int node = blockIdx.x * WPB + wi;
    int lane = threadIdx.x & 31;
    int beg = g_off[node], end = g_off[node + 1];
    float si_n = g_si[node];

    // pass 1: online softmax (fp32 si/sj — exact weights)
    float m = -1e30f, sum = 0.f;
    for (int i = beg + lane; i < end; i += 32) {
        int s = g_csr_src[i];
        float v = si_n + g_sj[s];
        float e = v > 0.f ? v : 0.2f * v;
        float mn = fmaxf(m, e);
        sum = sum * __expf(m - mn) + __expf(e - mn);
        m = mn;
    }
#pragma unroll
    for (int o = 16; o > 0; o >>= 1) {
        float mo = __shfl_xor_sync(0xffffffffu, m, o);
        float so = __shfl_xor_sync(0xffffffffu, sum, o);
        float mn = fmaxf(m, mo);
        sum = sum * __expf(m - mn) + so * __expf(mo - mn);
        m = mn;
    }
    float inv = 1.f / (sum + 1e-16f);

    // pass 2: alpha-weighted fp16 gather (uint2 = 4 halves per lane), batched 8
    float4 acc = make_float4(0.f, 0.f, 0.f, 0.f);
    for (int base = beg; base < end; base += 64) {
        int cnt = min(64, end - base);
        for (int i = lane; i < cnt; i += 32) {
            int s = g_csr_src[base + i];
            float v = si_n + g_sj[s];
            float e = v > 0.f ? v : 0.2f * v;
            sAlpha[wi][i] = __expf(e - m) * inv;
            sSrc[wi][i] = s;
        }
        __syncwarp();
        int i = 0;
        for (; i + 8 <= cnt; i += 8) {
            uint2 hv[8]; float a[8];
#pragma unroll
            for (int j = 0; j < 8; j++) {
                a[j]  = sAlpha[wi][i + j];
                hv[j] = ((const uint2*)h)[(size_t)sSrc[wi][i + j] * 32 + lane];
            }
#pragma unroll
            for (int j = 0; j < 8; j++) {
                float2 f0 = __half22float2(*(__half2*)&hv[j].x);
                float2 f1 = __half22float2(*(__half2*)&hv[j].y);
                acc.x = fmaf(a[j], f0.x, acc.x);
                acc.y = fmaf(a[j], f0.y, acc.y);
                acc.z = fmaf(a[j], f1.x, acc.z);
                acc.w = fmaf(a[j], f1.y, acc.w);
            }
        }
        for (; i < cnt; i++) {
            float a = sAlpha[wi][i];
            uint2 hv = ((const uint2*)h)[(size_t)sSrc[wi][i] * 32 + lane];
            float2 f0 = __half22float2(*(__half2*)&hv.x);
            float2 f1 = __half22float2(*(__half2*)&hv.y);
            acc.x = fmaf(a, f0.x, acc.x);
            acc.y = fmaf(a, f0.y, acc.y);
            acc.z = fmaf(a, f1.x, acc.z);
            acc.w = fmaf(a, f1.y, acc.w);
        }
        __syncwarp();
    }
    float4 b4 = ((const float4*)bias)[lane];
    float4 o4;
    o4.x = fmaxf(acc.x + b4.x, 0.f);
    o4.y = fmaxf(acc.y + b4.y, 0.f);
    o4.z = fmaxf(acc.z + b4.z, 0.f);
    o4.w = fmaxf(acc.w + b4.w, 0.f);
    ((float4*)out)[(size_t)node * 32 + lane] = o4;
}

// ---------------- combine final MLP ----------------
__global__ void k_combine(const float* __restrict__ Wp1, const float* __restrict__ bp1,
                          const float* __restrict__ Wp2, const float* __restrict__ bp2) {
    int c = blockIdx.x;
    int k = threadIdx.x;
    float s = 0.f;
    for (int mm = 0; mm < D; mm++) s = fmaf(Wp1[k * D + mm], Wp2[mm * OUTD + c], s);
    g_Wc[k * OUTD + c] = s;
    if (k == 0) {
        float b = bp2[c];
        for (int mm = 0; mm < D; mm++) b = fmaf(bp1[mm], Wp2[mm * OUTD + c], b);
        g_bc[c] = b;
    }
}

// ---------------- final GEMM + log_softmax ----------------
__global__ void __launch_bounds__(256, 4)
k_final(const float* __restrict__ x3, const float* __restrict__ Wc,
        const float* __restrict__ bc, float* __restrict__ out) {
    __shared__ float Xs[32][68];
    __shared__ float Ws[32][68];
    int t = threadIdx.x;
    int row0 = blockIdx.x * 64;
    int tx = t & 15, ty = t >> 4;
    float acc[4][4];
#pragma unroll
    for (int i = 0; i < 4; i++)
#pragma unroll
        for (int j = 0; j < 4; j++) acc[i][j] = 0.f;

    for (int kt = 0; kt < 4; kt++) {
#pragma unroll
        for (int l = 0; l < 2; l++) {
            int idx = t + l * 256;
            int r = idx >> 3;
            int kq = (idx & 7) * 4;
            int gr = row0 + r;
            float4 v = make_float4(0.f, 0.f, 0.f, 0.f);
            if (gr < NN) v = *(const float4*)&x3[(size_t)gr * D + kt * 32 + kq];
            Xs[kq + 0][r] = v.x; Xs[kq + 1][r] = v.y;
            Xs[kq + 2][r] = v.z; Xs[kq + 3][r] = v.w;
        }
#pragma unroll
        for (int l = 0; l < 2; l++) {
            int idx = t + l * 256;
            int r = idx >> 4;
            int cq = (idx & 15) * 4;
            *(float4*)&Ws[r][cq] = *(const float4*)&Wc[(size_t)(kt * 32 + r) * OUTD + cq];
        }
        __syncthreads();
#pragma unroll
        for (int kk = 0; kk < 32; kk++) {
            float4 av = *(float4*)&Xs[kk][ty * 4];
            float4 wv = *(float4*)&Ws[kk][tx * 4];
            float a[4] = {av.x, av.y, av.z, av.w};
            float w[4] = {wv.x, wv.y, wv.z, wv.w};
#pragma unroll
            for (int i = 0; i < 4; i++)
#pragma unroll
                for (int j = 0; j < 4; j++)
                    acc[i][j] = fmaf(a[i], w[j], acc[i][j]);
        }
        __syncthreads();
    }

    float b[4];
#pragma unroll
    for (int j = 0; j < 4; j++) b[j] = bc[tx * 4 + j];
#pragma unroll
    for (int i = 0; i < 4; i++) {
        float z[4];
        float m = -1e30f;
#pragma unroll
        for (int j = 0; j < 4; j++) { z[j] = acc[i][j] + b[j]; m = fmaxf(m, z[j]); }
#pragma unroll
        for (int o = 1; o < 16; o <<= 1) m = fmaxf(m, __shfl_xor_sync(0xffffffffu, m, o));
        float s = 0.f;
#pragma unroll
        for (int j = 0; j < 4; j++) s += __expf(z[j] - m);
#pragma unroll
        for (int o = 1; o < 16; o <<= 1) s += __shfl_xor_sync(0xffffffffu, s, o);
        float lg = m + __logf(s);
        int gr = row0 + ty * 4 + i;
        if (gr < NN) {
            float4 o4 = make_float4(z[0] - lg, z[1] - lg, z[2] - lg, z[3] - lg);
            *(float4*)&out[(size_t)gr * OUTD + tx * 4] = o4;
        }
    }
}

// ---------------- host launcher ----------------
extern "C" void kernel_launch(void* const* d_in, const int* in_sizes, int n_in,
                              void* d_out, int out_size) {
    const float* x      = (const float*)d_in[0];
    const void*  ei     = d_in[1];
    const float* Ws     = (const float*)d_in[2];
    const float* bs     = (const float*)d_in[3];
    const float* atts   = (const float*)d_in[4];
    const float* biases = (const float*)d_in[5];
    const float* Wp1    = (const float*)d_in[6];
    const float* bp1    = (const float*)d_in[7];
    const float* Wp2    = (const float*)d_in[8];
    const float* bp2    = (const float*)d_in[9];
    float* out = (float*)d_out;

    __half* h;
    float *bufA, *Wc, *bc;
    void* tmp;
    cudaGetSymbolAddress(&tmp, g_h);    h    = (__half*)tmp;
    cudaGetSymbolAddress(&tmp, g_bufA); bufA = (float*)tmp;
    cudaGetSymbolAddress(&tmp, g_Wc);   Wc   = (float*)tmp;
    cudaGetSymbolAddress(&tmp, g_bc);   bc   = (float*)tmp;

    k_detect<<<NBLK, 256>>>(ei);
    k_hist<<<(EE + 255) / 256, 256>>>(ei);
    k_gemm<<<(NN + 63) / 64, 128>>>(x, Ws, bs, atts, h, NN);   // layer-0 GEMM (CSR-independent)
    k_scanA<<<NBLK, 256>>>();
    k_scanC<<<NBLK, 256>>>();
    k_reorder<<<(EE + 255) / 256, 256>>>(ei);
    k_combine<<<OUTD, D>>>(Wp1, bp1, Wp2, bp2);

    for (int l = 0; l < 3; l++) {
        if (l > 0)
            k_gemm<<<(NN + 63) / 64, 128>>>(bufA, Ws + (size_t)l * D * D, bs + l * D,
                                            atts + (size_t)l * 2 * D, h, NN);
        k_edge<<<NN / WPB, WPB * 32>>>(h, biases + l * D, bufA);
    }
    k_final<<<(NN + 63) / 64, 256>>>(bufA, Wc, bc, out);
}

// round 12
// speedup vs baseline: 1.4703x; 1.4703x over previous
#include <cuda_runtime.h>
#include <cuda_bf16.h>
#include <math.h>

#define NN   50000
#define EE   600000
#define D    128
#define OUTD 64
#define NBLK ((NN + 255) / 256)

// ---------------- scratch (device globals; no allocation) ----------------
__device__ int      g_is64;
__device__ int      g_cnt[NN];
__device__ int      g_part[NBLK];
__device__ int      g_off[NN + 1];
__device__ int      g_fill[NN + 1];
__device__ int      g_csr_src[EE];
__device__ float    g_h   [(size_t)NN * D];
__device__ float    g_bufA[(size_t)NN * D];
__device__ float    g_si[NN];
__device__ float    g_sj[NN];
__device__ float    g_Wc[D * OUTD];
__device__ float    g_bc[OUTD];

// ---------------- detect dtype + zero histogram ----------------
__global__ void k_detect(const void* ei) {
    int i = blockIdx.x * 256 + threadIdx.x;
    if (i < NN) g_cnt[i] = 0;
    if (blockIdx.x == 0 && threadIdx.x < 32) {
        const long long* p = (const long long*)ei;
        long long v = p[threadIdx.x];
        int bad = (v < 0 || v >= NN) ? 1 : 0;
        unsigned b = __ballot_sync(0xffffffffu, bad);
        if (threadIdx.x == 0) g_is64 = (b == 0) ? 1 : 0;
    }
}

__device__ __forceinline__ void load_edge(const void* ei, int i, int& s, int& d) {
    if (g_is64) {
        const long long* p = (const long long*)ei;
        s = (int)p[i];
        d = (int)p[(size_t)EE + i];
    } else {
        const int* p = (const int*)ei;
        s = p[i];
        d = p[EE + i];
    }
}

__global__ void k_hist(const void* ei) {
    int i = blockIdx.x * blockDim.x + threadIdx.x;
    if (i >= EE) return;
    int d;
    if (g_is64) {
        const long long* p = (const long long*)ei;
        d = (int)p[(size_t)EE + i];
    } else {
        const int* p = (const int*)ei;
        d = p[EE + i];
    }
    atomicAdd(&g_cnt[d], 1);
}

// ---------------- scan ----------------
__global__ void k_scanA() {
    __shared__ int sw[8];
    int b = blockIdx.x;
    int i = b * 256 + threadIdx.x;
    int v = (i < NN) ? g_cnt[i] : 0;
    int lane = threadIdx.x & 31, wid = threadIdx.x >> 5;
#pragma unroll
    for (int o = 16; o > 0; o >>= 1) v += __shfl_xor_sync(0xffffffffu, v, o);
    if (lane == 0) sw[wid] = v;
    __syncthreads();
    if (threadIdx.x == 0) {
        int s = 0;
#pragma unroll
        for (int w = 0; w < 8; w++) s += sw[w];
        g_part[b] = s;
    }
}

__global__ void k_scanC() {
    __shared__ int sw[8];
    __shared__ int sbase;
    int b = blockIdx.x;
    int i = b * 256 + threadIdx.x;
    int lane = threadIdx.x & 31, wid = threadIdx.x >> 5;
    int v = (i < NN) ? g_cnt[i] : 0;
    int x = v;
#pragma unroll
    for (int o = 1; o < 32; o <<= 1) {
        int t = __shfl_up_sync(0xffffffffu, x, o);
        if (lane >= o) x += t;
    }
    if (lane == 31) sw[wid] = x;
    if (wid == 1) {
        int s = 0;
        for (int j = lane; j < b; j += 32) s += g_part[j];
#pragma unroll
        for (int o = 16; o > 0; o >>= 1) s += __shfl_xor_sync(0xffffffffu, s, o);
        if (lane == 0) sbase = s;
    }
    __syncthreads();
    if (wid == 0 && lane < 8) {
        int y = sw[lane];
#pragma unroll
        for (int o = 1; o < 8; o <<= 1) {
            int t = __shfl_up_sync(0xffu, y, o);
            if (lane >= o) y += t;
        }
        sw[lane] = y;
    }
    __syncthreads();
    int incl = x + (wid ? sw[wid - 1] : 0) + sbase;
    if (i < NN) { g_off[i + 1] = incl; g_fill[i + 1] = incl; }
    if (i == 0) { g_off[0] = 0; g_fill[0] = 0; }
}

__global__ void k_reorder(const void* ei) {
    int i = blockIdx.x * blockDim.x + threadIdx.x;
    if (i >= EE) return;
    int s, d;
    load_edge(ei, i, s, d);
    int pos = atomicAdd(&g_fill[d], 1);
    g_csr_src[pos] = s;
}

// ---------------- tf32 helpers ----------------
__device__ __forceinline__ unsigned f2tf32(float f) {
    unsigned u;
    asm("cvt.rna.tf32.f32 %0, %1;" : "=r"(u) : "f"(f));
    return u;
}
__device__ __forceinline__ uint2 split_tf32(float f) {
    unsigned hi = f2tf32(f);
    float r = f - __uint_as_float(hi);
    unsigned lo = f2tf32(r);
    return make_uint2(hi, lo);
}
__device__ __forceinline__ void mma8(float* c, unsigned a0, unsigned a1, unsigned a2, unsigned a3,
                                     unsigned b0, unsigned b1) {
    asm volatile("mma.sync.aligned.m16n8k8.row.col.f32.tf32.tf32.f32 "
                 "{%0,%1,%2,%3}, {%4,%5,%6,%7}, {%8,%9}, {%0,%1,%2,%3};"
                 : "+f"(c[0]), "+f"(c[1]), "+f"(c[2]), "+f"(c[3])
                 : "r"(a0), "r"(a1), "r"(a2), "r"(a3), "r"(b0), "r"(b1));
}

// ---------------- GEMM: 64x128 tile, 4 warps (2m x 2n), 3xTF32 mma ----------------
__global__ void __launch_bounds__(128)
k_gemm(const float* __restrict__ X, const float* __restrict__ W,
       const float* __restrict__ bias, const float* __restrict__ att,
       float* __restrict__ Y, int nrows) {
    __shared__ uint2 As[2][64][10];
    __shared__ uint2 Bs[2][8][132];
    __shared__ float sSi[64][2], sSj[64][2];

    int t = threadIdx.x;
    int lane = t & 31, wid = t >> 5;
    int warp_m = wid >> 1, warp_n = wid & 1;
    int g = lane >> 2, tc = lane & 3;
    int row0 = blockIdx.x * 64;

    float c[2][8][4];
#pragma unroll
    for (int mf = 0; mf < 2; mf++)
#pragma unroll
        for (int nf = 0; nf < 8; nf++)
#pragma unroll
            for (int q = 0; q < 4; q++) c[mf][nf][q] = 0.f;

    int a_row = t >> 1, a_kq = (t & 1) * 4;
    int b_k[2], b_nq[2];
#pragma unroll
    for (int l = 0; l < 2; l++) {
        int idx = t + l * 128;
        b_k[l]  = idx >> 5;
        b_nq[l] = (idx & 31) * 4;
    }

    float4 av, bv[2];
    {
        int gr = row0 + a_row;
        av = make_float4(0.f, 0.f, 0.f, 0.f);
        if (gr < nrows) av = *(const float4*)&X[(size_t)gr * D + a_kq];
#pragma unroll
        for (int l = 0; l < 2; l++)
            bv[l] = *(const float4*)&W[(size_t)b_k[l] * D + b_nq[l]];
    }
    {
        As[0][a_row][a_kq + 0] = split_tf32(av.x);
        As[0][a_row][a_kq + 1] = split_tf32(av.y);
        As[0][a_row][a_kq + 2] = split_tf32(av.z);
        As[0][a_row][a_kq + 3] = split_tf32(av.w);
#pragma unroll
        for (int l = 0; l < 2; l++) {
            Bs[0][b_k[l]][b_nq[l] + 0] = split_tf32(bv[l].x);
            Bs[0][b_k[l]][b_nq[l] + 1] = split_tf32(bv[l].y);
            Bs[0][b_k[l]][b_nq[l] + 2] = split_tf32(bv[l].z);
            Bs[0][b_k[l]][b_nq[l] + 3] = split_tf32(bv[l].w);
        }
    }
    __syncthreads();

    for (int kt = 0; kt < 16; kt++) {
        int cur = kt & 1;
        if (kt < 15) {
            int kb = (kt + 1) * 8;
            int gr = row0 + a_row;
            av = make_float4(0.f, 0.f, 0.f, 0.f);
            if (gr < nrows) av = *(const float4*)&X[(size_t)gr * D + kb + a_kq];
#pragma unroll
            for (int l = 0; l < 2; l++)
                bv[l] = *(const float4*)&W[(size_t)(kb + b_k[l]) * D + b_nq[l]];
        }
        unsigned ah[2][4], al[2][4];
#pragma unroll
        for (int mf = 0; mf < 2; mf++) {
            int r = warp_m * 32 + mf * 16 + g;
            uint2 x00 = As[cur][r][tc];
            uint2 x10 = As[cur][r + 8][tc];
            uint2 x01 = As[cur][r][tc + 4];
            uint2 x11 = As[cur][r + 8][tc + 4];
            ah[mf][0] = x00.x; ah[mf][1] = x10.x; ah[mf][2] = x01.x; ah[mf][3] = x11.x;
            al[mf][0] = x00.y; al[mf][1] = x10.y; al[mf][2] = x01.y; al[mf][3] = x11.y;
        }
#pragma unroll
        for (int nf = 0; nf < 8; nf++) {
            int n = warp_n * 64 + nf * 8 + g;
            uint2 y0 = Bs[cur][tc][n];
            uint2 y1 = Bs[cur][tc + 4][n];
#pragma unroll
            for (int mf = 0; mf < 2; mf++) {
                mma8(c[mf][nf], al[mf][0], al[mf][1], al[mf][2], al[mf][3], y0.x, y1.x); // lo*hi
                mma8(c[mf][nf], ah[mf][0], ah[mf][1], ah[mf][2], ah[mf][3], y0.y, y1.y); // hi*lo
                mma8(c[mf][nf], ah[mf][0], ah[mf][1], ah[mf][2], ah[mf][3], y0.x, y1.x); // hi*hi
            }
        }
        if (kt < 15) {
            int nxt = 1 - cur;
            As[nxt][a_row][a_kq + 0] = split_tf32(av.x);
            As[nxt][a_row][a_kq + 1] = split_tf32(av.y);
            As[nxt][a_row][a_kq + 2] = split_tf32(av.z);
            As[nxt][a_row][a_kq + 3] = split_tf32(av.w);
#pragma unroll
            for (int l = 0; l < 2; l++) {
                Bs[nxt][b_k[l]][b_nq[l] + 0] = split_tf32(bv[l].x);
                Bs[nxt][b_k[l]][b_nq[l] + 1] = split_tf32(bv[l].y);
                Bs[nxt][b_k[l]][b_nq[l] + 2] = split_tf32(bv[l].z);
                Bs[nxt][b_k[l]][b_nq[l] + 3] = split_tf32(bv[l].w);
            }
            __syncthreads();
        }
    }

#pragma unroll
    for (int mf = 0; mf < 2; mf++) {
        int rA = warp_m * 32 + mf * 16 + g;
        int rB = rA + 8;
        int grA = row0 + rA, grB = row0 + rB;
        float siA = 0.f, sjA = 0.f, siB = 0.f, sjB = 0.f;
#pragma unroll
        for (int nf = 0; nf < 8; nf++) {
            int col = warp_n * 64 + nf * 8 + tc * 2;
            float b0 = bias[col], b1 = bias[col + 1];
            float z0 = c[mf][nf][0] + b0, z1 = c[mf][nf][1] + b1;
            float z2 = c[mf][nf][2] + b0, z3 = c[mf][nf][3] + b1;
            if (grA < nrows) *(float2*)&Y[(size_t)grA * D + col] = make_float2(z0, z1);
            if (grB < nrows) *(float2*)&Y[(size_t)grB * D + col] = make_float2(z2, z3);
            float ai0 = att[col], ai1 = att[col + 1];
            float aj0 = att[D + col], aj1 = att[D + col + 1];
            siA = fmaf(z0, ai0, fmaf(z1, ai1, siA));
            sjA = fmaf(z0, aj0, fmaf(z1, aj1, sjA));
            siB = fmaf(z2, ai0, fmaf(z3, ai1, siB));
            sjB = fmaf(z2, aj0, fmaf(z3, aj1, sjB));
        }
#pragma unroll
        for (int o = 1; o < 4; o <<= 1) {
            siA += __shfl_xor_sync(0xffffffffu, siA, o);
            sjA += __shfl_xor_sync(0xffffffffu, sjA, o);
            siB += __shfl_xor_sync(0xffffffffu, siB, o);
            sjB += __shfl_xor_sync(0xffffffffu, sjB, o);
        }
        if (tc == 0) {
            sSi[rA][warp_n] = siA; sSj[rA][warp_n] = sjA;
            sSi[rB][warp_n] = siB; sSj[rB][warp_n] = sjB;
        }
    }
    __syncthreads();
    if (t < 64) {
        int gr = row0 + t;
        if (gr < nrows) {
            g_si[gr] = sSi[t][0] + sSi[t][1];
            g_sj[gr] = sSj[t][0] + sSj[t][1];
        }
    }
}

// ---------------- fused edge kernel: smem (src,e) stash for deg<=64 fast path ----------------
#define WPB 8
__global__ void k_edge(const float* __restrict__ h, const float* __restrict__ bias,
                       float* __restrict__ out) {
    __shared__ float sAlpha[WPB][64];
    __shared__ int   sSrc[WPB][64];
    int wi = threadIdx.x >> 5;
    int node = blockIdx.x * WPB + wi;
    int lane = threadIdx.x & 31;
    int beg = g_off[node], end = g_off[node + 1];
    int deg = end - beg;
    float si_n = g_si[node];
    float4 acc = make_float4(0.f, 0.f, 0.f, 0.f);

    if (deg > 0 && deg <= 64) {
        // ---- fast path: stash (src, e) in smem during pass 1 ----
        float m = -1e30f, sum = 0.f;
        for (int i = lane; i < deg; i += 32) {
            int s = g_csr_src[beg + i];
            float v = si_n + g_sj[s];
            float e = v > 0.f ? v : 0.2f * v;
            sSrc[wi][i] = s;
            sAlpha[wi][i] = e;
            float mn = fmaxf(m, e);
            sum = sum * __expf(m - mn) + __expf(e - mn);
            m = mn;
        }
#pragma unroll
        for (int o = 16; o > 0; o >>= 1) {
            float mo = __shfl_xor_sync(0xffffffffu, m, o);
            float so = __shfl_xor_sync(0xffffffffu, sum, o);
            float mn = fmaxf(m, mo);
            sum = sum * __expf(m - mn) + so * __expf(mo - mn);
            m = mn;
        }
        float inv = 1.f / (sum + 1e-16f);
        // convert stashed e -> alpha in-place
        for (int i = lane; i < deg; i += 32)
            sAlpha[wi][i] = __expf(sAlpha[wi][i] - m) * inv;
        __syncwarp();

        int i = 0;
        for (; i + 8 <= deg; i += 8) {
            float4 hv[8]; float a[8];
#pragma unroll
            for (int j = 0; j < 8; j++) {
                a[j]  = sAlpha[wi][i + j];
                hv[j] = ((const float4*)h)[(size_t)sSrc[wi][i + j] * 32 + lane];
            }
#pragma unroll
            for (int j = 0; j < 8; j++) {
                acc.x = fmaf(a[j], hv[j].x, acc.x);
                acc.y = fmaf(a[j], hv[j].y, acc.y);
                acc.z = fmaf(a[j], hv[j].z, acc.z);
                acc.w = fmaf(a[j], hv[j].w, acc.w);
            }
        }
        for (; i < deg; i++) {
            float a = sAlpha[wi][i];
            float4 hv = ((const float4*)h)[(size_t)sSrc[wi][i] * 32 + lane];
            acc.x = fmaf(a, hv.x, acc.x);
            acc.y = fmaf(a, hv.y, acc.y);
            acc.z = fmaf(a, hv.z, acc.z);
            acc.w = fmaf(a, hv.w, acc.w);
        }
    } else if (deg > 64) {
        // ---- general path (rare): recompute per chunk ----
        float m = -1e30f, sum = 0.f;
        for (int i = beg + lane; i < end; i += 32) {
            int s = g_csr_src[i];
            float v = si_n + g_sj[s];
            float e = v > 0.f ? v : 0.2f * v;
            float mn = fmaxf(m, e);
            sum = sum * __expf(m - mn) + __expf(e - mn);
            m = mn;
        }
#pragma unroll
        for (int o = 16; o > 0; o >>= 1) {
            float mo = __shfl_xor_sync(0xffffffffu, m, o);
            float so = __shfl_xor_sync(0xffffffffu, sum, o);
            float mn = fmaxf(m, mo);
            sum = sum * __expf(m - mn) + so * __expf(mo - mn);
            m = mn;
        }
        float inv = 1.f / (sum + 1e-16f);

        for (int base = beg; base < end; base += 64) {
            int cnt = min(64, end - base);
            for (int i = lane; i < cnt; i += 32) {
                int s = g_csr_src[base + i];
                float v = si_n + g_sj[s];
                float e = v > 0.f ? v : 0.2f * v;
                sAlpha[wi][i] = __expf(e - m) * inv;
                sSrc[wi][i] = s;
            }
            __syncwarp();
            int i = 0;
            for (; i + 8 <= cnt; i += 8) {
                float4 hv[8]; float a[8];
#pragma unroll
                for (int j = 0; j < 8; j++) {
                    a[j]  = sAlpha[wi][i + j];
                    hv[j] = ((const float4*)h)[(size_t)sSrc[wi][i + j] * 32 + lane];
                }
#pragma unroll
                for (int j = 0; j < 8; j++) {
                    acc.x = fmaf(a[j], hv[j].x, acc.x);
                    acc.y = fmaf(a[j], hv[j].y, acc.y);
                    acc.z = fmaf(a[j], hv[j].z, acc.z);
                    acc.w = fmaf(a[j], hv[j].w, acc.w);
                }
            }
            for (; i < cnt; i++) {
                float a = sAlpha[wi][i];
                float4 hv = ((const float4*)h)[(size_t)sSrc[wi][i] * 32 + lane];
                acc.x = fmaf(a, hv.x, acc.x);
                acc.y = fmaf(a, hv.y, acc.y);
                acc.z = fmaf(a, hv.z, acc.z);
                acc.w = fmaf(a, hv.w, acc.w);
            }
            __syncwarp();
        }
    }

    float4 b4 = ((const float4*)bias)[lane];
    float4 o4;
    o4.x = fmaxf(acc.x + b4.x, 0.f);
    o4.y = fmaxf(acc.y + b4.y, 0.f);
    o4.z = fmaxf(acc.z + b4.z, 0.f);
    o4.w = fmaxf(acc.w + b4.w, 0.f);
    ((float4*)out)[(size_t)node * 32 + lane] = o4;
}

// ---------------- combine final MLP ----------------
__global__ void k_combine(const float* __restrict__ Wp1, const float* __restrict__ bp1,
                          const float* __restrict__ Wp2, const float* __restrict__ bp2) {
    int c = blockIdx.x;
    int k = threadIdx.x;
    float s = 0.f;
    for (int mm = 0; mm < D; mm++) s = fmaf(Wp1[k * D + mm], Wp2[mm * OUTD + c], s);
    g_Wc[k * OUTD + c] = s;
    if (k == 0) {
        float b = bp2[c];
        for (int mm = 0; mm < D; mm++) b = fmaf(bp1[mm], Wp2[mm * OUTD + c], b);
        g_bc[c] = b;
    }
}

// ---------------- final GEMM + log_softmax ----------------
__global__ void __launch_bounds__(256, 4)
k_final(const float* __restrict__ x3, const float* __restrict__ Wc,
        const float* __restrict__ bc, float* __restrict__ out) {
    __shared__ float Xs[32][68];
    __shared__ float Ws[32][68];
    int t = threadIdx.x;
    int row0 = blockIdx.x * 64;
    int tx = t & 15, ty = t >> 4;
    float acc[4][4];
#pragma unroll
    for (int i = 0; i < 4; i++)
#pragma unroll
        for (int j = 0; j < 4; j++) acc[i][j] = 0.f;

    for (int kt = 0; kt < 4; kt++) {
#pragma unroll
        for (int l = 0; l < 2; l++) {
            int idx = t + l * 256;
            int r = idx >> 3;
            int kq = (idx & 7) * 4;
            int gr = row0 + r;
            float4 v = make_float4(0.f, 0.f, 0.f, 0.f);
            if (gr < NN) v = *(const float4*)&x3[(size_t)gr * D + kt * 32 + kq];
            Xs[kq + 0][r] = v.x; Xs[kq + 1][r] = v.y;
            Xs[kq + 2][r] = v.z; Xs[kq + 3][r] = v.w;
        }
#pragma unroll
        for (int l = 0; l < 2; l++) {
            int idx = t + l * 256;
            int r = idx >> 4;
            int cq = (idx & 15) * 4;
            *(float4*)&Ws[r][cq] = *(const float4*)&Wc[(size_t)(kt * 32 + r) * OUTD + cq];
        }
        __syncthreads();
#pragma unroll
        for (int kk = 0; kk < 32; kk++) {
            float4 av = *(float4*)&Xs[kk][ty * 4];
            float4 wv = *(float4*)&Ws[kk][tx * 4];
            float a[4] = {av.x, av.y, av.z, av.w};
            float w[4] = {wv.x, wv.y, wv.z, wv.w};
#pragma unroll
            for (int i = 0; i < 4; i++)
#pragma unroll
                for (int j = 0; j < 4; j++)
                    acc[i][j] = fmaf(a[i], w[j], acc[i][j]);
        }
        __syncthreads();
    }

    float b[4];
#pragma unroll
    for (int j = 0; j < 4; j++) b[j] = bc[tx * 4 + j];
#pragma unroll
    for (int i = 0; i < 4; i++) {
        float z[4];
        float m = -1e30f;
#pragma unroll
        for (int j = 0; j < 4; j++) { z[j] = acc[i][j] + b[j]; m = fmaxf(m, z[j]); }
#pragma unroll
        for (int o = 1; o < 16; o <<= 1) m = fmaxf(m, __shfl_xor_sync(0xffffffffu, m, o));
        float s = 0.f;
#pragma unroll
        for (int j = 0; j < 4; j++) s += __expf(z[j] - m);
#pragma unroll
        for (int o = 1; o < 16; o <<= 1) s += __shfl_xor_sync(0xffffffffu, s, o);
        float lg = m + __logf(s);
        int gr = row0 + ty * 4 + i;
        if (gr < NN) {
            float4 o4 = make_float4(z[0] - lg, z[1] - lg, z[2] - lg, z[3] - lg);
            *(float4*)&out[(size_t)gr * OUTD + tx * 4] = o4;
        }
    }
}

// ---------------- host launcher ----------------
extern "C" void kernel_launch(void* const* d_in, const int* in_sizes, int n_in,
                              void* d_out, int out_size) {
    const float* x      = (const float*)d_in[0];
    const void*  ei     = d_in[1];
    const float* Ws     = (const float*)d_in[2];
    const float* bs     = (const float*)d_in[3];
    const float* atts   = (const float*)d_in[4];
    const float* biases = (const float*)d_in[5];
    const float* Wp1    = (const float*)d_in[6];
    const float* bp1    = (const float*)d_in[7];
    const float* Wp2    = (const float*)d_in[8];
    const float* bp2    = (const float*)d_in[9];
    float* out = (float*)d_out;

    float *h, *bufA, *Wc, *bc;
    void* tmp;
    cudaGetSymbolAddress(&tmp, g_h);    h    = (float*)tmp;
    cudaGetSymbolAddress(&tmp, g_bufA); bufA = (float*)tmp;
    cudaGetSymbolAddress(&tmp, g_Wc);   Wc   = (float*)tmp;
    cudaGetSymbolAddress(&tmp, g_bc);   bc   = (float*)tmp;

    k_detect<<<NBLK, 256>>>(ei);
    k_hist<<<(EE + 255) / 256, 256>>>(ei);
    k_gemm<<<(NN + 63) / 64, 128>>>(x, Ws, bs, atts, h, NN);   // layer-0 GEMM (CSR-independent)
    k_scanA<<<NBLK, 256>>>();
    k_scanC<<<NBLK, 256>>>();
    k_reorder<<<(EE + 255) / 256, 256>>>(ei);
    k_combine<<<OUTD, D>>>(Wp1, bp1, Wp2, bp2);

    for (int l = 0; l < 3; l++) {
        if (l > 0)
            k_gemm<<<(NN + 63) / 64, 128>>>(bufA, Ws + (size_t)l * D * D, bs + l * D,
                                            atts + (size_t)l * 2 * D, h, NN);
        k_edge<<<NN / WPB, WPB * 32>>>(h, biases + l * D, bufA);
    }
    k_final<<<(NN + 63) / 64, 256>>>(bufA, Wc, bc, out);
}

// round 13
// speedup vs baseline: 1.5002x; 1.0203x over previous
#include <cuda_runtime.h>
#include <cuda_bf16.h>
#include <math.h>

#define NN   50000
#define EE   600000
#define D    128
#define OUTD 64
#define NBLK ((NN + 255) / 256)

// ---------------- scratch (device globals; no allocation) ----------------
__device__ int      g_is64;
__device__ int      g_cnt[NN];
__device__ int      g_part[NBLK];
__device__ int      g_off[NN + 1];
__device__ int      g_fill[NN + 1];
__device__ int      g_csr_src[EE];
__device__ float    g_h   [(size_t)NN * D];
__device__ float    g_bufA[(size_t)NN * D];
__device__ float    g_si[NN];
__device__ float    g_sj[NN];
__device__ float    g_Wc[D * OUTD];
__device__ float    g_bc[OUTD];

// ---------------- detect dtype + zero histogram ----------------
__global__ void k_detect(const void* ei) {
    int i = blockIdx.x * 256 + threadIdx.x;
    if (i < NN) g_cnt[i] = 0;
    if (blockIdx.x == 0 && threadIdx.x < 32) {
        const long long* p = (const long long*)ei;
        long long v = p[threadIdx.x];
        int bad = (v < 0 || v >= NN) ? 1 : 0;
        unsigned b = __ballot_sync(0xffffffffu, bad);
        if (threadIdx.x == 0) g_is64 = (b == 0) ? 1 : 0;
    }
}

// ---------------- histogram: 4 edges/thread (MLP=4) ----------------
__global__ void k_hist(const void* ei) {
    int i0 = (blockIdx.x * blockDim.x + threadIdx.x) * 4;
    if (i0 >= EE) return;
    int is64 = g_is64;
    int d[4];
    if (is64) {
        const long long* p = (const long long*)ei + EE;
#pragma unroll
        for (int q = 0; q < 4; q++) d[q] = (int)p[i0 + q];
    } else {
        const int* p = (const int*)ei + EE;
#pragma unroll
        for (int q = 0; q < 4; q++) d[q] = p[i0 + q];
    }
#pragma unroll
    for (int q = 0; q < 4; q++) atomicAdd(&g_cnt[d[q]], 1);
}

// ---------------- scan ----------------
__global__ void k_scanA() {
    __shared__ int sw[8];
    int b = blockIdx.x;
    int i = b * 256 + threadIdx.x;
    int v = (i < NN) ? g_cnt[i] : 0;
    int lane = threadIdx.x & 31, wid = threadIdx.x >> 5;
#pragma unroll
    for (int o = 16; o > 0; o >>= 1) v += __shfl_xor_sync(0xffffffffu, v, o);
    if (lane == 0) sw[wid] = v;
    __syncthreads();
    if (threadIdx.x == 0) {
        int s = 0;
#pragma unroll
        for (int w = 0; w < 8; w++) s += sw[w];
        g_part[b] = s;
    }
}

__global__ void k_scanC() {
    __shared__ int sw[8];
    __shared__ int sbase;
    int b = blockIdx.x;
    int i = b * 256 + threadIdx.x;
    int lane = threadIdx.x & 31, wid = threadIdx.x >> 5;
    int v = (i < NN) ? g_cnt[i] : 0;
    int x = v;
#pragma unroll
    for (int o = 1; o < 32; o <<= 1) {
        int t = __shfl_up_sync(0xffffffffu, x, o);
        if (lane >= o) x += t;
    }
    if (lane == 31) sw[wid] = x;
    if (wid == 1) {
        int s = 0;
        for (int j = lane; j < b; j += 32) s += g_part[j];
#pragma unroll
        for (int o = 16; o > 0; o >>= 1) s += __shfl_xor_sync(0xffffffffu, s, o);
        if (lane == 0) sbase = s;
    }
    __syncthreads();
    if (wid == 0 && lane < 8) {
        int y = sw[lane];
#pragma unroll
        for (int o = 1; o < 8; o <<= 1) {
            int t = __shfl_up_sync(0xffu, y, o);
            if (lane >= o) y += t;
        }
        sw[lane] = y;
    }
    __syncthreads();
    int incl = x + (wid ? sw[wid - 1] : 0) + sbase;
    if (i < NN) { g_off[i + 1] = incl; g_fill[i + 1] = incl; }
    if (i == 0) { g_off[0] = 0; g_fill[0] = 0; }
}

// ---------------- reorder: 4 edges/thread (MLP=4) ----------------
__global__ void k_reorder(const void* ei) {
    int i0 = (blockIdx.x * blockDim.x + threadIdx.x) * 4;
    if (i0 >= EE) return;
    int is64 = g_is64;
    int s[4], d[4];
    if (is64) {
        const long long* ps = (const long long*)ei;
        const long long* pd = ps + EE;
#pragma unroll
        for (int q = 0; q < 4; q++) { s[q] = (int)ps[i0 + q]; d[q] = (int)pd[i0 + q]; }
    } else {
        const int* ps = (const int*)ei;
        const int* pd = ps + EE;
#pragma unroll
        for (int q = 0; q < 4; q++) { s[q] = ps[i0 + q]; d[q] = pd[i0 + q]; }
    }
    int pos[4];
#pragma unroll
    for (int q = 0; q < 4; q++) pos[q] = atomicAdd(&g_fill[d[q]], 1);
#pragma unroll
    for (int q = 0; q < 4; q++) g_csr_src[pos[q]] = s[q];
}

// ---------------- tf32 helpers ----------------
__device__ __forceinline__ unsigned f2tf32(float f) {
    unsigned u;
    asm("cvt.rna.tf32.f32 %0, %1;" : "=r"(u) : "f"(f));
    return u;
}
__device__ __forceinline__ uint2 split_tf32(float f) {
    unsigned hi = f2tf32(f);
    float r = f - __uint_as_float(hi);
    unsigned lo = f2tf32(r);
    return make_uint2(hi, lo);
}
__device__ __forceinline__ void mma8(float* c, unsigned a0, unsigned a1, unsigned a2, unsigned a3,
                                     unsigned b0, unsigned b1) {
    asm volatile("mma.sync.aligned.m16n8k8.row.col.f32.tf32.tf32.f32 "
                 "{%0,%1,%2,%3}, {%4,%5,%6,%7}, {%8,%9}, {%0,%1,%2,%3};"
                 : "+f"(c[0]), "+f"(c[1]), "+f"(c[2]), "+f"(c[3])
                 : "r"(a0), "r"(a1), "r"(a2), "r"(a3), "r"(b0), "r"(b1));
}

// ---------------- GEMM: 64x128 tile, 4 warps (2m x 2n), 3xTF32 mma ----------------
__global__ void __launch_bounds__(128)
k_gemm(const float* __restrict__ X, const float* __restrict__ W,
       const float* __restrict__ bias, const float* __restrict__ att,
       float* __restrict__ Y, int nrows) {
    __shared__ uint2 As[2][64][10];
    __shared__ uint2 Bs[2][8][132];
    __shared__ float sSi[64][2], sSj[64][2];

    int t = threadIdx.x;
    int lane = t & 31, wid = t >> 5;
    int warp_m = wid >> 1, warp_n = wid & 1;
    int g = lane >> 2, tc = lane & 3;
    int row0 = blockIdx.x * 64;

    float c[2][8][4];
#pragma unroll
    for (int mf = 0; mf < 2; mf++)
#pragma unroll
        for (int nf = 0; nf < 8; nf++)
#pragma unroll
            for (int q = 0; q < 4; q++) c[mf][nf][q] = 0.f;

    int a_row = t >> 1, a_kq = (t & 1) * 4;
    int b_k[2], b_nq[2];
#pragma unroll
    for (int l = 0; l < 2; l++) {
        int idx = t + l * 128;
        b_k[l]  = idx >> 5;
        b_nq[l] = (idx & 31) * 4;
    }

    float4 av, bv[2];
    {
        int gr = row0 + a_row;
        av = make_float4(0.f, 0.f, 0.f, 0.f);
        if (gr < nrows) av = *(const float4*)&X[(size_t)gr * D + a_kq];
#pragma unroll
        for (int l = 0; l < 2; l++)
            bv[l] = *(const float4*)&W[(size_t)b_k[l] * D + b_nq[l]];
    }
    {
        As[0][a_row][a_kq + 0] = split_tf32(av.x);
        As[0][a_row][a_kq + 1] = split_tf32(av.y);
        As[0][a_row][a_kq + 2] = split_tf32(av.z);
        As[0][a_row][a_kq + 3] = split_tf32(av.w);
#pragma unroll
        for (int l = 0; l < 2; l++) {
            Bs[0][b_k[l]][b_nq[l] + 0] = split_tf32(bv[l].x);
            Bs[0][b_k[l]][b_nq[l] + 1] = split_tf32(bv[l].y);
            Bs[0][b_k[l]][b_nq[l] + 2] = split_tf32(bv[l].z);
            Bs[0][b_k[l]][b_nq[l] + 3] = split_tf32(bv[l].w);
        }
    }
    __syncthreads();

    for (int kt = 0; kt < 16; kt++) {
        int cur = kt & 1;
        if (kt < 15) {
            int kb = (kt + 1) * 8;
            int gr = row0 + a_row;
            av = make_float4(0.f, 0.f, 0.f, 0.f);
            if (gr < nrows) av = *(const float4*)&X[(size_t)gr * D + kb + a_kq];
#pragma unroll
            for (int l = 0; l < 2; l++)
                bv[l] = *(const float4*)&W[(size_t)(kb + b_k[l]) * D + b_nq[l]];
        }
        unsigned ah[2][4], al[2][4];
#pragma unroll
        for (int mf = 0; mf < 2; mf++) {
            int r = warp_m * 32 + mf * 16 + g;
            uint2 x00 = As[cur][r][tc];
            uint2 x10 = As[cur][r + 8][tc];
            uint2 x01 = As[cur][r][tc + 4];
            uint2 x11 = As[cur][r + 8][tc + 4];
            ah[mf][0] = x00.x; ah[mf][1] = x10.x; ah[mf][2] = x01.x; ah[mf][3] = x11.x;
            al[mf][0] = x00.y; al[mf][1] = x10.y; al[mf][2] = x01.y; al[mf][3] = x11.y;
        }
#pragma unroll
        for (int nf = 0; nf < 8; nf++) {
            int n = warp_n * 64 + nf * 8 + g;
            uint2 y0 = Bs[cur][tc][n];
            uint2 y1 = Bs[cur][tc + 4][n];
#pragma unroll
            for (int mf = 0; mf < 2; mf++) {
                mma8(c[mf][nf], al[mf][0], al[mf][1], al[mf][2], al[mf][3], y0.x, y1.x); // lo*hi
                mma8(c[mf][nf], ah[mf][0], ah[mf][1], ah[mf][2], ah[mf][3], y0.y, y1.y); // hi*lo
                mma8(c[mf][nf], ah[mf][0], ah[mf][1], ah[mf][2], ah[mf][3], y0.x, y1.x); // hi*hi
            }
        }
        if (kt < 15) {
            int nxt = 1 - cur;
            As[nxt][a_row][a_kq + 0] = split_tf32(av.x);
            As[nxt][a_row][a_kq + 1] = split_tf32(av.y);
            As[nxt][a_row][a_kq + 2] = split_tf32(av.z);
            As[nxt][a_row][a_kq + 3] = split_tf32(av.w);
#pragma unroll
            for (int l = 0; l < 2; l++) {
                Bs[nxt][b_k[l]][b_nq[l] + 0] = split_tf32(bv[l].x);
                Bs[nxt][b_k[l]][b_nq[l] + 1] = split_tf32(bv[l].y);
                Bs[nxt][b_k[l]][b_nq[l] + 2] = split_tf32(bv[l].z);
                Bs[nxt][b_k[l]][b_nq[l] + 3] = split_tf32(bv[l].w);
            }
            __syncthreads();
        }
    }

#pragma unroll
    for (int mf = 0; mf < 2; mf++) {
        int rA = warp_m * 32 + mf * 16 + g;
        int rB = rA + 8;
        int grA = row0 + rA, grB = row0 + rB;
        float siA = 0.f, sjA = 0.f, siB = 0.f, sjB = 0.f;
#pragma unroll
        for (int nf = 0; nf < 8; nf++) {
            int col = warp_n * 64 + nf * 8 + tc * 2;
            float b0 = bias[col], b1 = bias[col + 1];
            float z0 = c[mf][nf][0] + b0, z1 = c[mf][nf][1] + b1;
            float z2 = c[mf][nf][2] + b0, z3 = c[mf][nf][3] + b1;
            if (grA < nrows) *(float2*)&Y[(size_t)grA * D + col] = make_float2(z0, z1);
            if (grB < nrows) *(float2*)&Y[(size_t)grB * D + col] = make_float2(z2, z3);
            float ai0 = att[col], ai1 = att[col + 1];
            float aj0 = att[D + col], aj1 = att[D + col + 1];
            siA = fmaf(z0, ai0, fmaf(z1, ai1, siA));
            sjA = fmaf(z0, aj0, fmaf(z1, aj1, sjA));
            siB = fmaf(z2, ai0, fmaf(z3, ai1, siB));
            sjB = fmaf(z2, aj0, fmaf(z3, aj1, sjB));
        }
#pragma unroll
        for (int o = 1; o < 4; o <<= 1) {
            siA += __shfl_xor_sync(0xffffffffu, siA, o);
            sjA += __shfl_xor_sync(0xffffffffu, sjA, o);
            siB += __shfl_xor_sync(0xffffffffu, siB, o);
            sjB += __shfl_xor_sync(0xffffffffu, sjB, o);
        }
        if (tc == 0) {
            sSi[rA][warp_n] = siA; sSj[rA][warp_n] = sjA;
            sSi[rB][warp_n] = siB; sSj[rB][warp_n] = sjB;
        }
    }
    __syncthreads();
    if (t < 64) {
        int gr = row0 + t;
        if (gr < nrows) {
            g_si[gr] = sSi[t][0] + sSi[t][1];
            g_sj[gr] = sSj[t][0] + sSj[t][1];
        }
    }
}

// ---------------- fused edge kernel: smem (src,e) stash for deg<=64 fast path ----------------
#define WPB 8
__global__ void k_edge(const float* __restrict__ h, const float* __restrict__ bias,
                       float* __restrict__ out) {
    __shared__ float sAlpha[WPB][64];
    __shared__ int   sSrc[WPB][64];
    int wi = threadIdx.x >> 5;
    int node = blockIdx.x * WPB + wi;
    int lane = threadIdx.x & 31;
    int beg = g_off[node], end = g_off[node + 1];
    int deg = end - beg;
    float si_n = g_si[node];
    float4 acc = make_float4(0.f, 0.f, 0.f, 0.f);

    if (deg > 0 && deg <= 64) {
        float m = -1e30f, sum = 0.f;
        for (int i = lane; i < deg; i += 32) {
            int s = g_csr_src[beg + i];
            float v = si_n + g_sj[s];
            float e = v > 0.f ? v : 0.2f * v;
            sSrc[wi][i] = s;
            sAlpha[wi][i] = e;
            float mn = fmaxf(m, e);
            sum = sum * __expf(m - mn) + __expf(e - mn);
            m = mn;
        }
#pragma unroll
        for (int o = 16; o > 0; o >>= 1) {
            float mo = __shfl_xor_sync(0xffffffffu, m, o);
            float so = __shfl_xor_sync(0xffffffffu, sum, o);
            float mn = fmaxf(m, mo);
            sum = sum * __expf(m - mn) + so * __expf(mo - mn);
            m = mn;
        }
        float inv = 1.f / (sum + 1e-16f);
        for (int i = lane; i < deg; i += 32)
            sAlpha[wi][i] = __expf(sAlpha[wi][i] - m) * inv;
        __syncwarp();

        int i = 0;
        for (; i + 8 <= deg; i += 8) {
            float4 hv[8]; float a[8];
#pragma unroll
            for (int j = 0; j < 8; j++) {
                a[j]  = sAlpha[wi][i + j];
                hv[j] = ((const float4*)h)[(size_t)sSrc[wi][i + j] * 32 + lane];
            }
#pragma unroll
            for (int j = 0; j < 8; j++) {
                acc.x = fmaf(a[j], hv[j].x, acc.x);
                acc.y = fmaf(a[j], hv[j].y, acc.y);
                acc.z = fmaf(a[j], hv[j].z, acc.z);
                acc.w = fmaf(a[j], hv[j].w, acc.w);
            }
        }
        for (; i < deg; i++) {
            float a = sAlpha[wi][i];
            float4 hv = ((const float4*)h)[(size_t)sSrc[wi][i] * 32 + lane];
            acc.x = fmaf(a, hv.x, acc.x);
            acc.y = fmaf(a, hv.y, acc.y);
            acc.z = fmaf(a, hv.z, acc.z);
            acc.w = fmaf(a, hv.w, acc.w);
        }
    } else if (deg > 64) {
        float m = -1e30f, sum = 0.f;
        for (int i = beg + lane; i < end; i += 32) {
            int s = g_csr_src[i];
            float v = si_n + g_sj[s];
            float e = v > 0.f ? v : 0.2f * v;
            float mn = fmaxf(m, e);
            sum = sum * __expf(m - mn) + __expf(e - mn);
            m = mn;
        }
#pragma unroll
        for (int o = 16; o > 0; o >>= 1) {
            float mo = __shfl_xor_sync(0xffffffffu, m, o);
            float so = __shfl_xor_sync(0xffffffffu, sum, o);
            float mn = fmaxf(m, mo);
            sum = sum * __expf(m - mn) + so * __expf(mo - mn);
            m = mn;
        }
        float inv = 1.f / (sum + 1e-16f);

        for (int base = beg; base < end; base += 64) {
            int cnt = min(64, end - base);
            for (int i = lane; i < cnt; i += 32) {
                int s = g_csr_src[base + i];
                float v = si_n + g_sj[s];
                float e = v > 0.f ? v : 0.2f * v;
                sAlpha[wi][i] = __expf(e - m) * inv;
                sSrc[wi][i] = s;
            }
            __syncwarp();
            int i = 0;
            for (; i + 8 <= cnt; i += 8) {
                float4 hv[8]; float a[8];
#pragma unroll
                for (int j = 0; j < 8; j++) {
                    a[j]  = sAlpha[wi][i + j];
                    hv[j] = ((const float4*)h)[(size_t)sSrc[wi][i + j] * 32 + lane];
                }
#pragma unroll
                for (int j = 0; j < 8; j++) {
                    acc.x = fmaf(a[j], hv[j].x, acc.x);
                    acc.y = fmaf(a[j], hv[j].y, acc.y);
                    acc.z = fmaf(a[j], hv[j].z, acc.z);
                    acc.w = fmaf(a[j], hv[j].w, acc.w);
                }
            }
            for (; i < cnt; i++) {
                float a = sAlpha[wi][i];
                float4 hv = ((const float4*)h)[(size_t)sSrc[wi][i] * 32 + lane];
                acc.x = fmaf(a, hv.x, acc.x);
                acc.y = fmaf(a, hv.y, acc.y);
                acc.z = fmaf(a, hv.z, acc.z);
                acc.w = fmaf(a, hv.w, acc.w);
            }
            __syncwarp();
        }
    }

    float4 b4 = ((const float4*)bias)[lane];
    float4 o4;
    o4.x = fmaxf(acc.x + b4.x, 0.f);
    o4.y = fmaxf(acc.y + b4.y, 0.f);
    o4.z = fmaxf(acc.z + b4.z, 0.f);
    o4.w = fmaxf(acc.w + b4.w, 0.f);
    ((float4*)out)[(size_t)node * 32 + lane] = o4;
}

// ---------------- combine final MLP ----------------
__global__ void k_combine(const float* __restrict__ Wp1, const float* __restrict__ bp1,
                          const float* __restrict__ Wp2, const float* __restrict__ bp2) {
    int c = blockIdx.x;
    int k = threadIdx.x;
    float s = 0.f;
    for (int mm = 0; mm < D; mm++) s = fmaf(Wp1[k * D + mm], Wp2[mm * OUTD + c], s);
    g_Wc[k * OUTD + c] = s;
    if (k == 0) {
        float b = bp2[c];
        for (int mm = 0; mm < D; mm++) b = fmaf(bp1[mm], Wp2[mm * OUTD + c], b);
        g_bc[c] = b;
    }
}

// ---------------- final GEMM + log_softmax ----------------
__global__ void __launch_bounds__(256, 4)
k_final(const float* __restrict__ x3, const float* __restrict__ Wc,
        const float* __restrict__ bc, float* __restrict__ out) {
    __shared__ float Xs[32][68];
    __shared__ float Ws[32][68];
    int t = threadIdx.x;
    int row0 = blockIdx.x * 64;
    int tx = t & 15, ty = t >> 4;
    float acc[4][4];
#pragma unroll
    for (int i = 0; i < 4; i++)
#pragma unroll
        for (int j = 0; j < 4; j++) acc[i][j] = 0.f;

    for (int kt = 0; kt < 4; kt++) {
#pragma unroll
        for (int l = 0; l < 2; l++) {
            int idx = t + l * 256;
            int r = idx >> 3;
            int kq = (idx & 7) * 4;
            int gr = row0 + r;
            float4 v = make_float4(0.f, 0.f, 0.f, 0.f);
            if (gr < NN) v = *(const float4*)&x3[(size_t)gr * D + kt * 32 + kq];
            Xs[kq + 0][r] = v.x; Xs[kq + 1][r] = v.y;
            Xs[kq + 2][r] = v.z; Xs[kq + 3][r] = v.w;
        }
#pragma unroll
        for (int l = 0; l < 2; l++) {
            int idx = t + l * 256;
            int r = idx >> 4;
            int cq = (idx & 15) * 4;
            *(float4*)&Ws[r][cq] = *(const float4*)&Wc[(size_t)(kt * 32 + r) * OUTD + cq];
        }
        __syncthreads();
#pragma unroll
        for (int kk = 0; kk < 32; kk++) {
            float4 av = *(float4*)&Xs[kk][ty * 4];
            float4 wv = *(float4*)&Ws[kk][tx * 4];
            float a[4] = {av.x, av.y, av.z, av.w};
            float w[4] = {wv.x, wv.y, wv.z, wv.w};
#pragma unroll
            for (int i = 0; i < 4; i++)
#pragma unroll
                for (int j = 0; j < 4; j++)
                    acc[i][j] = fmaf(a[i], w[j], acc[i][j]);
        }
        __syncthreads();
    }

    float b[4];
#pragma unroll
    for (int j = 0; j < 4; j++) b[j] = bc[tx * 4 + j];
#pragma unroll
    for (int i = 0; i < 4; i++) {
        float z[4];
        float m = -1e30f;
#pragma unroll
        for (int j = 0; j < 4; j++) { z[j] = acc[i][j] + b[j]; m = fmaxf(m, z[j]); }
#pragma unroll
        for (int o = 1; o < 16; o <<= 1) m = fmaxf(m, __shfl_xor_sync(0xffffffffu, m, o));
        float s = 0.f;
#pragma unroll
        for (int j = 0; j < 4; j++) s += __expf(z[j] - m);
#pragma unroll
        for (int o = 1; o < 16; o <<= 1) s += __shfl_xor_sync(0xffffffffu, s, o);
        float lg = m + __logf(s);
        int gr = row0 + ty * 4 + i;
        if (gr < NN) {
            float4 o4 = make_float4(z[0] - lg, z[1] - lg, z[2] - lg, z[3] - lg);
            *(float4*)&out[(size_t)gr * OUTD + tx * 4] = o4;
        }
    }
}

// ---------------- host launcher ----------------
extern "C" void kernel_launch(void* const* d_in, const int* in_sizes, int n_in,
                              void* d_out, int out_size) {
    const float* x      = (const float*)d_in[0];
    const void*  ei     = d_in[1];
    const float* Ws     = (const float*)d_in[2];
    const float* bs     = (const float*)d_in[3];
    const float* atts   = (const float*)d_in[4];
    const float* biases = (const float*)d_in[5];
    const float* Wp1    = (const float*)d_in[6];
    const float* bp1    = (const float*)d_in[7];
    const float* Wp2    = (const float*)d_in[8];
    const float* bp2    = (const float*)d_in[9];
    float* out = (float*)d_out;

    float *h, *bufA, *Wc, *bc;
    void* tmp;
    cudaGetSymbolAddress(&tmp, g_h);    h    = (float*)tmp;
    cudaGetSymbolAddress(&tmp, g_bufA); bufA = (float*)tmp;
    cudaGetSymbolAddress(&tmp, g_Wc);   Wc   = (float*)tmp;
    cudaGetSymbolAddress(&tmp, g_bc);   bc   = (float*)tmp;

    // launch order: 0 detect, 1 hist, 2 scanA, 3 gemm(l0) <- ncu slot, 4 scanC, 5 reorder
    k_detect<<<NBLK, 256>>>(ei);
    k_hist<<<(EE / 4 + 255) / 256, 256>>>(ei);
    k_scanA<<<NBLK, 256>>>();
    k_gemm<<<(NN + 63) / 64, 128>>>(x, Ws, bs, atts, h, NN);   // layer-0 GEMM (CSR-independent)
    k_scanC<<<NBLK, 256>>>();
    k_reorder<<<(EE / 4 + 255) / 256, 256>>>(ei);
    k_combine<<<OUTD, D>>>(Wp1, bp1, Wp2, bp2);

    for (int l = 0; l < 3; l++) {
        if (l > 0)
            k_gemm<<<(NN + 63) / 64, 128>>>(bufA, Ws + (size_t)l * D * D, bs + l * D,
                                            atts + (size_t)l * 2 * D, h, NN);
        k_edge<<<NN / WPB, WPB * 32>>>(h, biases + l * D, bufA);
    }
    k_final<<<(NN + 63) / 64, 256>>>(bufA, Wc, bc, out);
}

// round 16
// speedup vs baseline: 1.7636x; 1.1756x over previous
#include <cuda_runtime.h>
#include <cuda_bf16.h>
#include <math.h>

#define NN   50000
#define EE   600000
#define D    128
#define OUTD 64
#define NBLK ((NN + 255) / 256)

// ---------------- scratch (device globals; no allocation) ----------------
__device__ int      g_is64;
__device__ int      g_cnt[NN];
__device__ int      g_part[NBLK];
__device__ int      g_off[NN + 1];
__device__ int      g_fill[NN + 1];
__device__ int      g_csr_src[EE];
__device__ float    g_h   [(size_t)NN * D];
__device__ float    g_bufA[(size_t)NN * D];
__device__ float    g_si[NN];
__device__ float    g_sj[NN];
__device__ float    g_Wc[D * OUTD];
__device__ float    g_bc[OUTD];
__device__ uint2    g_Wt[3 * 8192];   // per layer: [kc 0..15][tc 0..3][n 0..127] pair=(W[8kc+tc][n], W[8kc+tc+4][n]) as tf32

// ---------------- detect dtype + zero histogram ----------------
__global__ void k_detect(const void* ei) {
    int i = blockIdx.x * 256 + threadIdx.x;
    if (i < NN) g_cnt[i] = 0;
    if (blockIdx.x == 0 && threadIdx.x < 32) {
        const long long* p = (const long long*)ei;
        long long v = p[threadIdx.x];
        int bad = (v < 0 || v >= NN) ? 1 : 0;
        unsigned b = __ballot_sync(0xffffffffu, bad);
        if (threadIdx.x == 0) g_is64 = (b == 0) ? 1 : 0;
    }
}

// ---------------- histogram: 4 edges/thread (MLP=4) ----------------
__global__ void k_hist(const void* ei) {
    int i0 = (blockIdx.x * blockDim.x + threadIdx.x) * 4;
    if (i0 >= EE) return;
    int is64 = g_is64;
    int d[4];
    if (is64) {
        const long long* p = (const long long*)ei + EE;
#pragma unroll
        for (int q = 0; q < 4; q++) d[q] = (int)p[i0 + q];
    } else {
        const int* p = (const int*)ei + EE;
#pragma unroll
        for (int q = 0; q < 4; q++) d[q] = p[i0 + q];
    }
#pragma unroll
    for (int q = 0; q < 4; q++) atomicAdd(&g_cnt[d[q]], 1);
}

// ---------------- tf32 helper ----------------
__device__ __forceinline__ unsigned f2tf32(float f) {
    unsigned u;
    asm("cvt.rna.tf32.f32 %0, %1;" : "=r"(u) : "f"(f));
    return u;
}
__device__ __forceinline__ void mma8(float* c, unsigned a0, unsigned a1, unsigned a2, unsigned a3,
                                     unsigned b0, unsigned b1) {
    asm volatile("mma.sync.aligned.m16n8k8.row.col.f32.tf32.tf32.f32 "
                 "{%0,%1,%2,%3}, {%4,%5,%6,%7}, {%8,%9}, {%0,%1,%2,%3};"
                 : "+f"(c[0]), "+f"(c[1]), "+f"(c[2]), "+f"(c[3])
                 : "r"(a0), "r"(a1), "r"(a2), "r"(a3), "r"(b0), "r"(b1));
}

// ---------------- W -> tf32 pre-paired layout ----------------
__global__ void k_cvtW(const float* __restrict__ Ws) {
    int idx = blockIdx.x * 256 + threadIdx.x;
    if (idx >= 3 * 8192) return;
    int l   = idx >> 13;
    int rem = idx & 8191;
    int kc  = rem >> 9;
    int r2  = rem & 511;
    int tc  = r2 >> 7;
    int n   = r2 & 127;
    const float* W = Ws + (size_t)l * D * D;
    float w0 = W[(kc * 8 + tc) * D + n];
    float w1 = W[(kc * 8 + tc + 4) * D + n];
    g_Wt[idx] = make_uint2(f2tf32(w0), f2tf32(w1));
}

// ---------------- scan ----------------
__global__ void k_scanA() {
    __shared__ int sw[8];
    int b = blockIdx.x;
    int i = b * 256 + threadIdx.x;
    int v = (i < NN) ? g_cnt[i] : 0;
    int lane = threadIdx.x & 31, wid = threadIdx.x >> 5;
#pragma unroll
    for (int o = 16; o > 0; o >>= 1) v += __shfl_xor_sync(0xffffffffu, v, o);
    if (lane == 0) sw[wid] = v;
    __syncthreads();
    if (threadIdx.x == 0) {
        int s = 0;
#pragma unroll
        for (int w = 0; w < 8; w++) s += sw[w];
        g_part[b] = s;
    }
}

__global__ void k_scanC() {
    __shared__ int sw[8];
    __shared__ int sbase;
    int b = blockIdx.x;
    int i = b * 256 + threadIdx.x;
    int lane = threadIdx.x & 31, wid = threadIdx.x >> 5;
    int v = (i < NN) ? g_cnt[i] : 0;
    int x = v;
#pragma unroll
    for (int o = 1; o < 32; o <<= 1) {
        int t = __shfl_up_sync(0xffffffffu, x, o);
        if (lane >= o) x += t;
    }
    if (lane == 31) sw[wid] = x;
    if (wid == 1) {
        int s = 0;
        for (int j = lane; j < b; j += 32) s += g_part[j];
#pragma unroll
        for (int o = 16; o > 0; o >>= 1) s += __shfl_xor_sync(0xffffffffu, s, o);
        if (lane == 0) sbase = s;
    }
    __syncthreads();
    if (wid == 0 && lane < 8) {
        int y = sw[lane];
#pragma unroll
        for (int o = 1; o < 8; o <<= 1) {
            int t = __shfl_up_sync(0xffu, y, o);
            if (lane >= o) y += t;
        }
        sw[lane] = y;
    }
    __syncthreads();
    int incl = x + (wid ? sw[wid - 1] : 0) + sbase;
    if (i < NN) { g_off[i + 1] = incl; g_fill[i + 1] = incl; }
    if (i == 0) { g_off[0] = 0; g_fill[0] = 0; }
}

// ---------------- reorder: 4 edges/thread ----------------
__global__ void k_reorder(const void* ei) {
    int i0 = (blockIdx.x * blockDim.x + threadIdx.x) * 4;
    if (i0 >= EE) return;
    int is64 = g_is64;
    int s[4], d[4];
    if (is64) {
        const long long* ps = (const long long*)ei;
        const long long* pd = ps + EE;
#pragma unroll
        for (int q = 0; q < 4; q++) { s[q] = (int)ps[i0 + q]; d[q] = (int)pd[i0 + q]; }
    } else {
        const int* ps = (const int*)ei;
        const int* pd = ps + EE;
#pragma unroll
        for (int q = 0; q < 4; q++) { s[q] = ps[i0 + q]; d[q] = pd[i0 + q]; }
    }
    int pos[4];
#pragma unroll
    for (int q = 0; q < 4; q++) pos[q] = atomicAdd(&g_fill[d[q]], 1);
#pragma unroll
    for (int q = 0; q < 4; q++) g_csr_src[pos[q]] = s[q];
}

// ---------------- GEMM: 64x128 tile, 4 warps, pure TF32, paired fragments ----------------
__global__ void __launch_bounds__(128)
k_gemm(const float* __restrict__ X, const uint2* __restrict__ Wt,
       const float* __restrict__ bias, const float* __restrict__ att,
       float* __restrict__ Y, int nrows) {
    __shared__ uint2 Ap[2][64][6];    // [row][tc] pair = (A[r][tc], A[r][tc+4]); stride 48B (16-aligned)
    __shared__ uint2 Bf[2][16][33];   // fragment layout: [nf_global][lane] pair = (B[tc][n], B[tc+4][n])
    __shared__ float sSi[64][2], sSj[64][2];

    int t = threadIdx.x;
    int lane = t & 31, wid = t >> 5;
    int warp_m = wid >> 1, warp_n = wid & 1;
    int g = lane >> 2, tc = lane & 3;
    int row0 = blockIdx.x * 64;

    float c[2][8][4];
#pragma unroll
    for (int mf = 0; mf < 2; mf++)
#pragma unroll
        for (int nf = 0; nf < 8; nf++)
#pragma unroll
            for (int q = 0; q < 4; q++) c[mf][nf][q] = 0.f;

    // staging roles: warps 0-1 stage A (one row each), warps 2-3 stage B
    bool roleA = t < 64;
    int arow = t;                 // 0..63 (roleA)
    int u = t - 64;               // 0..63 (roleB)
    int btc = u >> 4;             // 0..3
    int bn0 = (u & 15) * 8;       // 0..120, multiple of 8 -> one nf
    int bnf = bn0 >> 3;

    float4 ax, ay;
    uint4 bx[4];

    // ---- prologue: load chunk 0 into regs ----
    if (roleA) {
        int gr = row0 + arow;
        ax = make_float4(0.f, 0.f, 0.f, 0.f);
        ay = ax;
        if (gr < nrows) {
            ax = *(const float4*)&X[(size_t)gr * D + 0];
            ay = *(const float4*)&X[(size_t)gr * D + 4];
        }
    } else {
        const uint2* src = Wt + btc * 128 + bn0;
#pragma unroll
        for (int q = 0; q < 4; q++) bx[q] = *(const uint4*)(src + q * 2);
    }
    // ---- store chunk 0 ----
    if (roleA) {
        uint2 p0 = make_uint2(f2tf32(ax.x), f2tf32(ay.x));
        uint2 p1 = make_uint2(f2tf32(ax.y), f2tf32(ay.y));
        uint2 p2 = make_uint2(f2tf32(ax.z), f2tf32(ay.z));
        uint2 p3 = make_uint2(f2tf32(ax.w), f2tf32(ay.w));
        *(uint4*)&Ap[0][arow][0] = make_uint4(p0.x, p0.y, p1.x, p1.y);
        *(uint4*)&Ap[0][arow][2] = make_uint4(p2.x, p2.y, p3.x, p3.y);
    } else {
#pragma unroll
        for (int q = 0; q < 4; q++) {
            Bf[0][bnf][(2 * q + 0) * 4 + btc] = make_uint2(bx[q].x, bx[q].y);
            Bf[0][bnf][(2 * q + 1) * 4 + btc] = make_uint2(bx[q].z, bx[q].w);
        }
    }
    __syncthreads();

    for (int kt = 0; kt < 16; kt++) {
        int cur = kt & 1;
        if (kt < 15) {
            if (roleA) {
                int gr = row0 + arow;
                ax = make_float4(0.f, 0.f, 0.f, 0.f);
                ay = ax;
                if (gr < nrows) {
                    ax = *(const float4*)&X[(size_t)gr * D + (kt + 1) * 8 + 0];
                    ay = *(const float4*)&X[(size_t)gr * D + (kt + 1) * 8 + 4];
                }
            } else {
                const uint2* src = Wt + (kt + 1) * 512 + btc * 128 + bn0;
#pragma unroll
                for (int q = 0; q < 4; q++) bx[q] = *(const uint4*)(src + q * 2);
            }
        }
        // ---- MMA on cur ----
        unsigned a[2][4];
#pragma unroll
        for (int mf = 0; mf < 2; mf++) {
            int r = warp_m * 32 + mf * 16 + g;
            uint2 p0 = Ap[cur][r][tc];
            uint2 p1 = Ap[cur][r + 8][tc];
            a[mf][0] = p0.x; a[mf][1] = p1.x; a[mf][2] = p0.y; a[mf][3] = p1.y;
        }
#pragma unroll
        for (int nf = 0; nf < 8; nf++) {
            uint2 b = Bf[cur][warp_n * 8 + nf][lane];
            mma8(c[0][nf], a[0][0], a[0][1], a[0][2], a[0][3], b.x, b.y);
            mma8(c[1][nf], a[1][0], a[1][1], a[1][2], a[1][3], b.x, b.y);
        }
        if (kt < 15) {
            int nxt = 1 - cur;
            if (roleA) {
                uint2 p0 = make_uint2(f2tf32(ax.x), f2tf32(ay.x));
                uint2 p1 = make_uint2(f2tf32(ax.y), f2tf32(ay.y));
                uint2 p2 = make_uint2(f2tf32(ax.z), f2tf32(ay.z));
                uint2 p3 = make_uint2(f2tf32(ax.w), f2tf32(ay.w));
                *(uint4*)&Ap[nxt][arow][0] = make_uint4(p0.x, p0.y, p1.x, p1.y);
                *(uint4*)&Ap[nxt][arow][2] = make_uint4(p2.x, p2.y, p3.x, p3.y);
            } else {
#pragma unroll
                for (int q = 0; q < 4; q++) {
                    Bf[nxt][bnf][(2 * q + 0) * 4 + btc] = make_uint2(bx[q].x, bx[q].y);
                    Bf[nxt][bnf][(2 * q + 1) * 4 + btc] = make_uint2(bx[q].z, bx[q].w);
                }
            }
            __syncthreads();
        }
    }

    // ---- epilogue: bias add, Y store, si/sj reduction ----
#pragma unroll
    for (int mf = 0; mf < 2; mf++) {
        int rA = warp_m * 32 + mf * 16 + g;
        int rB = rA + 8;
        int grA = row0 + rA, grB = row0 + rB;
        float siA = 0.f, sjA = 0.f, siB = 0.f, sjB = 0.f;
#pragma unroll
        for (int nf = 0; nf < 8; nf++) {
            int col = warp_n * 64 + nf * 8 + tc * 2;
            float b0 = bias[col], b1 = bias[col + 1];
            float z0 = c[mf][nf][0] + b0, z1 = c[mf][nf][1] + b1;
            float z2 = c[mf][nf][2] + b0, z3 = c[mf][nf][3] + b1;
            if (grA < nrows) *(float2*)&Y[(size_t)grA * D + col] = make_float2(z0, z1);
            if (grB < nrows) *(float2*)&Y[(size_t)grB * D + col] = make_float2(z2, z3);
            float ai0 = att[col], ai1 = att[col + 1];
            float aj0 = att[D + col], aj1 = att[D + col + 1];
            siA = fmaf(z0, ai0, fmaf(z1, ai1, siA));
            sjA = fmaf(z0, aj0, fmaf(z1, aj1, sjA));
            siB = fmaf(z2, ai0, fmaf(z3, ai1, siB));
            sjB = fmaf(z2, aj0, fmaf(z3, aj1, sjB));
        }
#pragma unroll
        for (int o = 1; o < 4; o <<= 1) {
            siA += __shfl_xor_sync(0xffffffffu, siA, o);
            sjA += __shfl_xor_sync(0xffffffffu, sjA, o);
            siB += __shfl_xor_sync(0xffffffffu, siB, o);
            sjB += __shfl_xor_sync(0xffffffffu, sjB, o);
        }
        if (tc == 0) {
            sSi[rA][warp_n] = siA; sSj[rA][warp_n] = sjA;
            sSi[rB][warp_n] = siB; sSj[rB][warp_n] = sjB;
        }
    }
    __syncthreads();
    if (t < 64) {
        int gr = row0 + t;
        if (gr < nrows) {
            g_si[gr] = sSi[t][0] + sSi[t][1];
            g_sj[gr] = sSj[t][0] + sSj[t][1];
        }
    }
}

// ---------------- fused edge kernel (unchanged from 299us build) ----------------
#define WPB 8
__global__ void k_edge(const float* __restrict__ h, const float* __restrict__ bias,
                       float* __restrict__ out) {
    __shared__ float sAlpha[WPB][64];
    __shared__ int   sSrc[WPB][64];
    int wi = threadIdx.x >> 5;
    int node = blockIdx.x * WPB + wi;
    int lane = threadIdx.x & 31;
    int beg = g_off[node], end = g_off[node + 1];
    int deg = end - beg;
    float si_n = g_si[node];
    float4 acc = make_float4(0.f, 0.f, 0.f, 0.f);

    if (deg > 0 && deg <= 64) {
        float m = -1e30f, sum = 0.f;
        for (int i = lane; i < deg; i += 32) {
            int s = g_csr_src[beg + i];
            float v = si_n + g_sj[s];
            float e = v > 0.f ? v : 0.2f * v;
            sSrc[wi][i] = s;
            sAlpha[wi][i] = e;
            float mn = fmaxf(m, e);
            sum = sum * __expf(m - mn) + __expf(e - mn);
            m = mn;
        }
#pragma unroll
        for (int o = 16; o > 0; o >>= 1) {
            float mo = __shfl_xor_sync(0xffffffffu, m, o);
            float so = __shfl_xor_sync(0xffffffffu, sum, o);
            float mn = fmaxf(m, mo);
            sum = sum * __expf(m - mn) + so * __expf(mo - mn);
            m = mn;
        }
        float inv = 1.f / (sum + 1e-16f);
        for (int i = lane; i < deg; i += 32)
            sAlpha[wi][i] = __expf(sAlpha[wi][i] - m) * inv;
        __syncwarp();

        int i = 0;
        for (; i + 8 <= deg; i += 8) {
            float4 hv[8]; float a[8];
#pragma unroll
            for (int j = 0; j < 8; j++) {
                a[j]  = sAlpha[wi][i + j];
                hv[j] = ((const float4*)h)[(size_t)sSrc[wi][i + j] * 32 + lane];
            }
#pragma unroll
            for (int j = 0; j < 8; j++) {
                acc.x = fmaf(a[j], hv[j].x, acc.x);
                acc.y = fmaf(a[j], hv[j].y, acc.y);
                acc.z = fmaf(a[j], hv[j].z, acc.z);
                acc.w = fmaf(a[j], hv[j].w, acc.w);
            }
        }
        for (; i < deg; i++) {
            float a = sAlpha[wi][i];
            float4 hv = ((const float4*)h)[(size_t)sSrc[wi][i] * 32 + lane];
            acc.x = fmaf(a, hv.x, acc.x);
            acc.y = fmaf(a, hv.y, acc.y);
            acc.z = fmaf(a, hv.z, acc.z);
            acc.w = fmaf(a, hv.w, acc.w);
        }
    } else if (deg > 64) {
        float m = -1e30f, sum = 0.f;
        for (int i = beg + lane; i < end; i += 32) {
            int s = g_csr_src[i];
            float v = si_n + g_sj[s];
            float e = v > 0.f ? v : 0.2f * v;
            float mn = fmaxf(m, e);
            sum = sum * __expf(m - mn) + __expf(e - mn);
            m = mn;
        }
#pragma unroll
        for (int o = 16; o > 0; o >>= 1) {
            float mo = __shfl_xor_sync(0xffffffffu, m, o);
            float so = __shfl_xor_sync(0xffffffffu, sum, o);
            float mn = fmaxf(m, mo);
            sum = sum * __expf(m - mn) + so * __expf(mo - mn);
            m = mn;
        }
        float inv = 1.f / (sum + 1e-16f);

        for (int base = beg; base < end; base += 64) {
            int cnt = min(64, end - base);
            for (int i = lane; i < cnt; i += 32) {
                int s = g_csr_src[base + i];
                float v = si_n + g_sj[s];
                float e = v > 0.f ? v : 0.2f * v;
                sAlpha[wi][i] = __expf(e - m) * inv;
                sSrc[wi][i] = s;
            }
            __syncwarp();
            int i = 0;
            for (; i + 8 <= cnt; i += 8) {
                float4 hv[8]; float a[8];
#pragma unroll
                for (int j = 0; j < 8; j++) {
                    a[j]  = sAlpha[wi][i + j];
                    hv[j] = ((const float4*)h)[(size_t)sSrc[wi][i + j] * 32 + lane];
                }
#pragma unroll
                for (int j = 0; j < 8; j++) {
                    acc.x = fmaf(a[j], hv[j].x, acc.x);
                    acc.y = fmaf(a[j], hv[j].y, acc.y);
                    acc.z = fmaf(a[j], hv[j].z, acc.z);
                    acc.w = fmaf(a[j], hv[j].w, acc.w);
                }
            }
            for (; i < cnt; i++) {
                float a = sAlpha[wi][i];
                float4 hv = ((const float4*)h)[(size_t)sSrc[wi][i] * 32 + lane];
                acc.x = fmaf(a, hv.x, acc.x);
                acc.y = fmaf(a, hv.y, acc.y);
                acc.z = fmaf(a, hv.z, acc.z);
                acc.w = fmaf(a, hv.w, acc.w);
            }
            __syncwarp();
        }
    }

    float4 b4 = ((const float4*)bias)[lane];
    float4 o4;
    o4.x = fmaxf(acc.x + b4.x, 0.f);
    o4.y = fmaxf(acc.y + b4.y, 0.f);
    o4.z = fmaxf(acc.z + b4.z, 0.f);
    o4.w = fmaxf(acc.w + b4.w, 0.f);
    ((float4*)out)[(size_t)node * 32 + lane] = o4;
}

// ---------------- combine final MLP ----------------
__global__ void k_combine(const float* __restrict__ Wp1, const float* __restrict__ bp1,
                          const float* __restrict__ Wp2, const float* __restrict__ bp2) {
    int c = blockIdx.x;
    int k = threadIdx.x;
    float s = 0.f;
    for (int mm = 0; mm < D; mm++) s = fmaf(Wp1[k * D + mm], Wp2[mm * OUTD + c], s);
    g_Wc[k * OUTD + c] = s;
    if (k == 0) {
        float b = bp2[c];
        for (int mm = 0; mm < D; mm++) b = fmaf(bp1[mm], Wp2[mm * OUTD + c], b);
        g_bc[c] = b;
    }
}

// ---------------- final GEMM + log_softmax ----------------
__global__ void __launch_bounds__(256, 4)
k_final(const float* __restrict__ x3, const float* __restrict__ Wc,
        const float* __restrict__ bc, float* __restrict__ out) {
    __shared__ float Xs[32][68];
    __shared__ float Ws[32][68];
    int t = threadIdx.x;
    int row0 = blockIdx.x * 64;
    int tx = t & 15, ty = t >> 4;
    float acc[4][4];
#pragma unroll
    for (int i = 0; i < 4; i++)
#pragma unroll
        for (int j = 0; j < 4; j++) acc[i][j] = 0.f;

    for (int kt = 0; kt < 4; kt++) {
#pragma unroll
        for (int l = 0; l < 2; l++) {
            int idx = t + l * 256;
            int r = idx >> 3;
            int kq = (idx & 7) * 4;
            int gr = row0 + r;
            float4 v = make_float4(0.f, 0.f, 0.f, 0.f);
            if (gr < NN) v = *(const float4*)&x3[(size_t)gr * D + kt * 32 + kq];
            Xs[kq + 0][r] = v.x; Xs[kq + 1][r] = v.y;
            Xs[kq + 2][r] = v.z; Xs[kq + 3][r] = v.w;
        }
#pragma unroll
        for (int l = 0; l < 2; l++) {
            int idx = t + l * 256;
            int r = idx >> 4;
            int cq = (idx & 15) * 4;
            *(float4*)&Ws[r][cq] = *(const float4*)&Wc[(size_t)(kt * 32 + r) * OUTD + cq];
        }
        __syncthreads();
#pragma unroll
        for (int kk = 0; kk < 32; kk++) {
            float4 av = *(float4*)&Xs[kk][ty * 4];
            float4 wv = *(float4*)&Ws[kk][tx * 4];
            float a[4] = {av.x, av.y, av.z, av.w};
            float w[4] = {wv.x, wv.y, wv.z, wv.w};
#pragma unroll
            for (int i = 0; i < 4; i++)
#pragma unroll
                for (int j = 0; j < 4; j++)
                    acc[i][j] = fmaf(a[i], w[j], acc[i][j]);
        }
        __syncthreads();
    }

    float b[4];
#pragma unroll
    for (int j = 0; j < 4; j++) b[j] = bc[tx * 4 + j];
#pragma unroll
    for (int i = 0; i < 4; i++) {
        float z[4];
        float m = -1e30f;
#pragma unroll
        for (int j = 0; j < 4; j++) { z[j] = acc[i][j] + b[j]; m = fmaxf(m, z[j]); }
#pragma unroll
        for (int o = 1; o < 16; o <<= 1) m = fmaxf(m, __shfl_xor_sync(0xffffffffu, m, o));
        float s = 0.f;
#pragma unroll
        for (int j = 0; j < 4; j++) s += __expf(z[j] - m);
#pragma unroll
        for (int o = 1; o < 16; o <<= 1) s += __shfl_xor_sync(0xffffffffu, s, o);
        float lg = m + __logf(s);
        int gr = row0 + ty * 4 + i;
        if (gr < NN) {
            float4 o4 = make_float4(z[0] - lg, z[1] - lg, z[2] - lg, z[3] - lg);
            *(float4*)&out[(size_t)gr * OUTD + tx * 4] = o4;
        }
    }
}

// ---------------- host launcher ----------------
extern "C" void kernel_launch(void* const* d_in, const int* in_sizes, int n_in,
                              void* d_out, int out_size) {
    const float* x      = (const float*)d_in[0];
    const void*  ei     = d_in[1];
    const float* Ws     = (const float*)d_in[2];
    const float* bs     = (const float*)d_in[3];
    const float* atts   = (const float*)d_in[4];
    const float* biases = (const float*)d_in[5];
    const float* Wp1    = (const float*)d_in[6];
    const float* bp1    = (const float*)d_in[7];
    const float* Wp2    = (const float*)d_in[8];
    const float* bp2    = (const float*)d_in[9];
    float* out = (float*)d_out;

    float *h, *bufA, *Wc, *bc;
    uint2* Wt;
    void* tmp;
    cudaGetSymbolAddress(&tmp, g_h);    h    = (float*)tmp;
    cudaGetSymbolAddress(&tmp, g_bufA); bufA = (float*)tmp;
    cudaGetSymbolAddress(&tmp, g_Wc);   Wc   = (float*)tmp;
    cudaGetSymbolAddress(&tmp, g_bc);   bc   = (float*)tmp;
    cudaGetSymbolAddress(&tmp, g_Wt);   Wt   = (uint2*)tmp;

    // launch order: 0 detect, 1 hist, 2 cvtW, 3 gemm(l0) <- ncu slot
    k_detect<<<NBLK, 256>>>(ei);
    k_hist<<<(EE / 4 + 255) / 256, 256>>>(ei);
    k_cvtW<<<96, 256>>>(Ws);
    k_gemm<<<(NN + 63) / 64, 128>>>(x, Wt, bs, atts, h, NN);   // layer-0 GEMM
    k_scanA<<<NBLK, 256>>>();
    k_scanC<<<NBLK, 256>>>();
    k_reorder<<<(EE / 4 + 255) / 256, 256>>>(ei);
    k_combine<<<OUTD, D>>>(Wp1, bp1, Wp2, bp2);

    for (int l = 0; l < 3; l++) {
        if (l > 0)
            k_gemm<<<(NN + 63) / 64, 128>>>(bufA, Wt + (size_t)l * 8192, bs + l * D,
                                            atts + (size_t)l * 2 * D, h, NN);
        k_edge<<<NN / WPB, WPB * 32>>>(h, biases + l * D, bufA);
    }
    k_final<<<(NN + 63) / 64, 256>>>(bufA, Wc, bc, out);
}